// round 7
// baseline (speedup 1.0000x reference)
#include <cuda_runtime.h>
#include <cstdint>
#include <math.h>

#define B_DIM  1024
#define H_DIM  1024
#define KPAD   1024

#define ASTR 36                         // smem floats/row, 36%32==4 -> conflict-free frag LDS
#define TILE_BYTES (128 * ASTR * 4)     // 18432 (A: 128 m-rows; B: 128 n-rows)
#define ST1_BYTES (2 * TILE_BYTES)      // kernel1 stage: A + B
#define ST2_BYTES (3 * TILE_BYTES)      // kernel2 stage: A + B0 + B1
#define NSTAGE 4
#define SMEM1 (NSTAGE * ST1_BYTES)      // 147456
#define SMEM2 (NSTAGE * ST2_BYTES)      // 221184
#define HIDS 132

// tf32-pre-rounded operands (zero-init pads K=1000 -> 1024)
__device__ float cvt_core[B_DIM * KPAD];
__device__ float cvt_h[B_DIM * KPAD];
__device__ float cvt_concept[B_DIM * KPAD];
__device__ float cvt_Win[4 * H_DIM * KPAD];
__device__ float cvt_Wst[4 * H_DIM * KPAD];
__device__ float cvt_Wci[4 * H_DIM * KPAD];
__device__ float cvt_Wcs[4 * H_DIM * KPAD];
// fragment-layout scratch: xi, hs  ([cta][wid][t][lane] float4)
__device__ float g_xi[B_DIM * 4 * H_DIM];
__device__ float g_hs[B_DIM * 4 * H_DIM];

__device__ __forceinline__ uint32_t smem_u32(const void* p) {
    uint32_t a;
    asm("{ .reg .u64 t; cvta.to.shared.u64 t, %1; cvt.u32.u64 %0, t; }" : "=r"(a) : "l"(p));
    return a;
}
__device__ __forceinline__ void cpa16(uint32_t dst, const float* src) {
    asm volatile("cp.async.cg.shared.global [%0], [%1], 16;"
                 :: "r"(dst), "l"(__cvta_generic_to_global(src)) : "memory");
}
#define CP_COMMIT() asm volatile("cp.async.commit_group;" ::: "memory")
#define CP_WAIT2()  asm volatile("cp.async.wait_group 2;" ::: "memory")

__device__ __forceinline__ void mma8(float* d, const uint32_t* a, const uint32_t* b) {
    asm volatile(
        "mma.sync.aligned.m16n8k8.row.col.f32.tf32.tf32.f32 "
        "{%0,%1,%2,%3}, {%4,%5,%6,%7}, {%8,%9}, {%0,%1,%2,%3};"
        : "+f"(d[0]), "+f"(d[1]), "+f"(d[2]), "+f"(d[3])
        : "r"(a[0]), "r"(a[1]), "r"(a[2]), "r"(a[3]), "r"(b[0]), "r"(b[1]));
}

// Warp tile 64(M) x 32(N), K=32 chunk. As[m][k], Bs[n][k], stride ASTR.
__device__ __forceinline__ void compute_chunk(const uint32_t* As, const uint32_t* Bs,
                                              float (&acc)[64],
                                              int wm, int wn, int gid, int ctid) {
    const uint32_t* Aw = As + (wm * 64 + gid) * ASTR + ctid;
    const uint32_t* Bw = Bs + (wn * 32 + gid) * ASTR + ctid;
#pragma unroll
    for (int ks = 0; ks < 4; ks++) {
        uint32_t bf[4][2];
#pragma unroll
        for (int nt = 0; nt < 4; nt++) {
            bf[nt][0] = Bw[nt * 8 * ASTR + ks * 8];
            bf[nt][1] = Bw[nt * 8 * ASTR + ks * 8 + 4];
        }
#pragma unroll
        for (int mt = 0; mt < 4; mt++) {
            uint32_t af[4];
            af[0] = Aw[(mt * 16    ) * ASTR + ks * 8];
            af[1] = Aw[(mt * 16 + 8) * ASTR + ks * 8];
            af[2] = Aw[(mt * 16    ) * ASTR + ks * 8 + 4];
            af[3] = Aw[(mt * 16 + 8) * ASTR + ks * 8 + 4];
#pragma unroll
            for (int nt = 0; nt < 4; nt++)
                mma8(&acc[(mt * 4 + nt) * 4], af, bf[nt]);
        }
    }
}

// Dual-B chunk: shared A fragments, two accumulator sets.
__device__ __forceinline__ void compute_chunk2(const uint32_t* As, const uint32_t* B0s,
                                               const uint32_t* B1s,
                                               float (&acc0)[64], float (&acc1)[64],
                                               int wm, int wn, int gid, int ctid) {
    const uint32_t* Aw  = As  + (wm * 64 + gid) * ASTR + ctid;
    const uint32_t* Bw0 = B0s + (wn * 32 + gid) * ASTR + ctid;
    const uint32_t* Bw1 = B1s + (wn * 32 + gid) * ASTR + ctid;
#pragma unroll
    for (int ks = 0; ks < 4; ks++) {
        uint32_t bf0[4][2], bf1[4][2];
#pragma unroll
        for (int nt = 0; nt < 4; nt++) {
            bf0[nt][0] = Bw0[nt * 8 * ASTR + ks * 8];
            bf0[nt][1] = Bw0[nt * 8 * ASTR + ks * 8 + 4];
            bf1[nt][0] = Bw1[nt * 8 * ASTR + ks * 8];
            bf1[nt][1] = Bw1[nt * 8 * ASTR + ks * 8 + 4];
        }
#pragma unroll
        for (int mt = 0; mt < 4; mt++) {
            uint32_t af[4];
            af[0] = Aw[(mt * 16    ) * ASTR + ks * 8];
            af[1] = Aw[(mt * 16 + 8) * ASTR + ks * 8];
            af[2] = Aw[(mt * 16    ) * ASTR + ks * 8 + 4];
            af[3] = Aw[(mt * 16 + 8) * ASTR + ks * 8 + 4];
#pragma unroll
            for (int nt = 0; nt < 4; nt++) {
                mma8(&acc0[(mt * 4 + nt) * 4], af, bf0[nt]);
                mma8(&acc1[(mt * 4 + nt) * 4], af, bf1[nt]);
            }
        }
    }
}

// cp.async a [128 x 32] tile. lrow = tid>>1 (0..127), lkg = tid&1.
__device__ __forceinline__ void cp_tile_A(uint32_t st, const float* A, int brow0,
                                          int k0, int lrow, int lkg) {
    const float* g = A + (size_t)(brow0 + lrow) * KPAD + k0 + lkg * 16;
    uint32_t d = st + (uint32_t)((lrow * ASTR + lkg * 16) * 4);
#pragma unroll
    for (int i = 0; i < 4; i++) cpa16(d + i * 16, g + i * 4);
}
__device__ __forceinline__ void cp_tile_B(uint32_t st, const float* W, int hcol0,
                                          int k0, int lrow, int lkg) {
    int rg = ((lrow >> 5) << 10) + hcol0 + (lrow & 31);   // gate row = sec*1024 + hcol
    const float* g = W + (size_t)rg * KPAD + k0 + lkg * 16;
    uint32_t d = st + (uint32_t)((lrow * ASTR + lkg * 16) * 4);
#pragma unroll
    for (int i = 0; i < 4; i++) cpa16(d + i * 16, g + i * 4);
}

// ---------------- kernel1: xi = core@Win, hs = h@Wst -> scratch ----------------
__global__ void __launch_bounds__(256) scn_k1(void) {
    extern __shared__ float smf[];
    const uint32_t sbase = smem_u32(smf);
    const int tid = threadIdx.x, lane = tid & 31, wid = tid >> 5;
    const int gid = lane >> 2, ctid = lane & 3;
    const int wm = wid >> 2, wn = wid & 3;
    const int lrow = tid >> 1, lkg = tid & 1;
    const int hcol0 = blockIdx.x * 32;
    const int brow0 = blockIdx.y * 128;
    const int cta = blockIdx.y * 32 + blockIdx.x;

    float axi[64] = {}, ahs[64] = {};

    auto issue = [&](int g) {
        uint32_t st = sbase + (uint32_t)(g & 3) * ST1_BYTES;
        int k0 = (g & 31) * 32;
        cp_tile_A(st, (g < 32) ? cvt_core : cvt_h, brow0, k0, lrow, lkg);
        cp_tile_B(st + TILE_BYTES, (g < 32) ? cvt_Win : cvt_Wst, hcol0, k0, lrow, lkg);
        CP_COMMIT();
    };
    issue(0); issue(1); issue(2);

    for (int g = 0; g < 64; g++) {
        CP_WAIT2();
        __syncthreads();
        if (g + 3 < 64) issue(g + 3); else CP_COMMIT();
        const uint32_t* st = (const uint32_t*)smf + (size_t)(g & 3) * (ST1_BYTES / 4);
        if (g < 32) compute_chunk(st, st + TILE_BYTES / 4, axi, wm, wn, gid, ctid);
        else        compute_chunk(st, st + TILE_BYTES / 4, ahs, wm, wn, gid, ctid);
    }

    // store fragments coalesced: float4 index ((cta*8+wid)*16 + t)*32 + lane
    float4* xs = (float4*)g_xi;
    float4* hss = (float4*)g_hs;
    size_t base = ((size_t)(cta * 8 + wid) * 16) * 32 + lane;
#pragma unroll
    for (int t = 0; t < 16; t++) {
        xs[base + (size_t)t * 32]  = make_float4(axi[t*4], axi[t*4+1], axi[t*4+2], axi[t*4+3]);
        hss[base + (size_t)t * 32] = make_float4(ahs[t*4], ahs[t*4+1], ahs[t*4+2], ahs[t*4+3]);
    }
}

// ------- kernel2: gi = concept@Wci, gs = concept@Wcs (dual-B) + full epilogue -------
__global__ void __launch_bounds__(256) scn_k2(const float* __restrict__ c_state,
                                              float* __restrict__ out) {
    extern __shared__ float smf[];
    const uint32_t sbase = smem_u32(smf);
    const int tid = threadIdx.x, lane = tid & 31, wid = tid >> 5;
    const int gid = lane >> 2, ctid = lane & 3;
    const int wm = wid >> 2, wn = wid & 3;
    const int lrow = tid >> 1, lkg = tid & 1;
    const int hcol0 = blockIdx.x * 32;
    const int brow0 = blockIdx.y * 128;
    const int cta = blockIdx.y * 32 + blockIdx.x;

    float agi[64] = {}, ags[64] = {};

    auto issue = [&](int g) {
        uint32_t st = sbase + (uint32_t)(g & 3) * ST2_BYTES;
        int k0 = (g & 31) * 32;
        cp_tile_A(st, cvt_concept, brow0, k0, lrow, lkg);
        cp_tile_B(st + TILE_BYTES,     cvt_Wci, hcol0, k0, lrow, lkg);
        cp_tile_B(st + 2 * TILE_BYTES, cvt_Wcs, hcol0, k0, lrow, lkg);
        CP_COMMIT();
    };
    issue(0); issue(1); issue(2);

    for (int g = 0; g < 32; g++) {
        CP_WAIT2();
        __syncthreads();
        if (g + 3 < 32) issue(g + 3); else CP_COMMIT();
        const uint32_t* st = (const uint32_t*)smf + (size_t)(g & 3) * (ST2_BYTES / 4);
        compute_chunk2(st, st + TILE_BYTES / 4, st + 2 * (TILE_BYTES / 4),
                       agi, ags, wm, wn, gid, ctid);
    }
    __syncthreads();

    // ---- epilogue: z = gi*xi + gs*hs, sigmoid -> hid smem ----
    float* hid = smf;   // 128 x HIDS
    const float4* xs = (const float4*)g_xi;
    const float4* hss = (const float4*)g_hs;
    size_t base = ((size_t)(cta * 8 + wid) * 16) * 32 + lane;
#pragma unroll
    for (int t = 0; t < 16; t++) {
        float4 x4 = xs[base + (size_t)t * 32];
        float4 h4 = hss[base + (size_t)t * 32];
        const float zx[4] = {x4.x, x4.y, x4.z, x4.w};
        const float zh[4] = {h4.x, h4.y, h4.z, h4.w};
        int mt = t >> 2, nt = t & 3;
#pragma unroll
        for (int c = 0; c < 4; c++) {
            float z = agi[t * 4 + c] * zx[c] + ags[t * 4 + c] * zh[c];
            int m = wm * 64 + mt * 16 + gid + ((c >> 1) ? 8 : 0);
            int n = wn * 32 + nt * 8 + ctid * 2 + (c & 1);
            hid[m * HIDS + n] = 1.0f / (1.0f + expf(-z));
        }
    }
    __syncthreads();

    // ---- LSTM combine: n = sec*32 + jl ----
    {
        int m = tid >> 1;
        int j0 = (tid & 1) * 16;
        const float* row = hid + m * HIDS;
        size_t gbase = (size_t)(brow0 + m) * H_DIM + hcol0 + j0;
#pragma unroll
        for (int q = 0; q < 4; q++) {
            float4 hv, cv;
            float* ph = (float*)&hv;
            float* pc = (float*)&cv;
#pragma unroll
            for (int r = 0; r < 4; r++) {
                int j = j0 + q * 4 + r;
                float it = row[j];
                float ft = row[32 + j];
                float ot = row[64 + j];
                float cc = row[96 + j];
                float cs = c_state[gbase - j0 + j];
                float ct = it * cc + ft * cs;
                pc[r] = ct;
                ph[r] = ot * tanhf(ct);
            }
            *(float4*)&out[gbase + q * 4] = hv;
            *(float4*)&out[(size_t)B_DIM * H_DIM + gbase + q * 4] = cv;
        }
    }
}

// ---------------- tf32 round + pad pre-pass ----------------
template <int J>
__global__ void __launch_bounds__(256) cvt_kernel(const float4* __restrict__ src,
                                                  int n4, int c4) {
    int i = blockIdx.x * blockDim.x + threadIdx.x;
    if (i >= n4) return;
    float4 v = src[i];
    uint32_t a, b, c, e;
    asm("cvt.rna.tf32.f32 %0, %1;" : "=r"(a) : "f"(v.x));
    asm("cvt.rna.tf32.f32 %0, %1;" : "=r"(b) : "f"(v.y));
    asm("cvt.rna.tf32.f32 %0, %1;" : "=r"(c) : "f"(v.z));
    asm("cvt.rna.tf32.f32 %0, %1;" : "=r"(e) : "f"(v.w));
    float4 o;
    o.x = __uint_as_float(a); o.y = __uint_as_float(b);
    o.z = __uint_as_float(c); o.w = __uint_as_float(e);
    float* dst = (J == 0) ? cvt_core : (J == 1) ? cvt_h : (J == 2) ? cvt_concept
               : (J == 3) ? cvt_Win  : (J == 4) ? cvt_Wst
               : (J == 5) ? cvt_Wci  : cvt_Wcs;
    int row = i / c4, col = i - row * c4;
    ((float4*)dst)[row * (KPAD / 4) + col] = o;
}

template <int J>
static void launch_cvt(const float* src, int rows, int cols) {
    int n4 = rows * cols / 4;
    cvt_kernel<J><<<(n4 + 255) / 256, 256>>>((const float4*)src, n4, cols / 4);
}

extern "C" void kernel_launch(void* const* d_in, const int* in_sizes, int n_in,
                              void* d_out, int out_size) {
    const float* core_input = (const float*)d_in[0];
    const float* h_state    = (const float*)d_in[1];
    const float* c_state    = (const float*)d_in[2];
    const float* concept    = (const float*)d_in[3];
    const float* W_in       = (const float*)d_in[4];
    const float* W_st       = (const float*)d_in[5];
    const float* W_ci       = (const float*)d_in[6];
    const float* W_cs       = (const float*)d_in[7];
    float* out = (float*)d_out;

    static bool configured = false;
    if (!configured) {
        cudaFuncSetAttribute(scn_k1, cudaFuncAttributeMaxDynamicSharedMemorySize, SMEM1);
        cudaFuncSetAttribute(scn_k2, cudaFuncAttributeMaxDynamicSharedMemorySize, SMEM2);
        configured = true;
    }

    launch_cvt<0>(core_input, B_DIM, 1024);
    launch_cvt<1>(h_state,    B_DIM, 1024);
    launch_cvt<2>(concept,    B_DIM, 1000);
    launch_cvt<3>(W_in,  4 * H_DIM, 1024);
    launch_cvt<4>(W_st,  4 * H_DIM, 1024);
    launch_cvt<5>(W_ci,  4 * H_DIM, 1000);
    launch_cvt<6>(W_cs,  4 * H_DIM, 1000);

    dim3 grid(32, 8);   // 32 hcol tiles x 8 batch tiles = 256 CTAs
    scn_k1<<<grid, 256, SMEM1>>>();
    scn_k2<<<grid, 256, SMEM2>>>(c_state, out);
}

// round 8
// speedup vs baseline: 1.0167x; 1.0167x over previous
#include <cuda_runtime.h>
#include <cstdint>
#include <math.h>

#define B_DIM 1024
#define H_DIM 1024
#define KPAD  1024

// fragment-major blocks: A (m16-block, kchunk32) = 512 floats = 2048 B
//                        W (n8-block,  kchunk32) = 256 floats = 1024 B
#define A_STG 16384                    // 8 m16-blocks * 2048 B
#define B_STG 8192                     // 8 n8-blocks * 1024 B
#define STAGE_BYTES (A_STG + 2 * B_STG)   // 32768
#define NSTAGE 4
#define SMEM_BYTES (NSTAGE * STAGE_BYTES) // 131072
#define HID_STRIDE 65

// fragment-major, tf32-pre-rounded operands (pads K=1000 -> 1024 with explicit 0)
__device__ float rA_core[B_DIM * KPAD];
__device__ float rA_h[B_DIM * KPAD];
__device__ float rA_concept[B_DIM * KPAD];
__device__ float rW_in[4 * H_DIM * KPAD];
__device__ float rW_st[4 * H_DIM * KPAD];
__device__ float rW_ci[4 * H_DIM * KPAD];
__device__ float rW_cs[4 * H_DIM * KPAD];

__device__ __forceinline__ uint32_t smem_u32(const void* p) {
    uint32_t a;
    asm("{ .reg .u64 t; cvta.to.shared.u64 t, %1; cvt.u32.u64 %0, t; }" : "=r"(a) : "l"(p));
    return a;
}
__device__ __forceinline__ void cpa16(uint32_t dst, const float* src) {
    asm volatile("cp.async.cg.shared.global [%0], [%1], 16;"
                 :: "r"(dst), "l"(__cvta_generic_to_global(src)) : "memory");
}
#define CP_COMMIT() asm volatile("cp.async.commit_group;" ::: "memory")
#define CP_WAIT2()  asm volatile("cp.async.wait_group 2;" ::: "memory")

__device__ __forceinline__ void mma8(float* d, const uint32_t* a, const uint32_t* b) {
    asm volatile(
        "mma.sync.aligned.m16n8k8.row.col.f32.tf32.tf32.f32 "
        "{%0,%1,%2,%3}, {%4,%5,%6,%7}, {%8,%9}, {%0,%1,%2,%3};"
        : "+f"(d[0]), "+f"(d[1]), "+f"(d[2]), "+f"(d[3])
        : "r"(a[0]), "r"(a[1]), "r"(a[2]), "r"(a[3]), "r"(b[0]), "r"(b[1]));
}

__device__ __forceinline__ uint32_t tf32r(float x) {
    uint32_t r;
    asm("cvt.rna.tf32.f32 %0, %1;" : "=r"(r) : "f"(x));
    return r;
}

// Warp tile 64(M) x 16(N): fragment loads are single LDS.128 / LDS.64.
__device__ __forceinline__ void cchunk(const char* st, float (&acc)[32],
                                       int wm, int wn, int lane) {
    const char* Ab = st + wm * 4 * 2048 + lane * 16;
    const char* Bb = st + A_STG + wn * 2 * 1024 + lane * 8;
#pragma unroll
    for (int ks = 0; ks < 4; ks++) {
        uint2 bf0 = *(const uint2*)(Bb + ks * 256);
        uint2 bf1 = *(const uint2*)(Bb + 1024 + ks * 256);
#pragma unroll
        for (int mt = 0; mt < 4; mt++) {
            uint4 af = *(const uint4*)(Ab + mt * 2048 + ks * 512);
            mma8(&acc[mt * 8],     (const uint32_t*)&af, (const uint32_t*)&bf0);
            mma8(&acc[mt * 8 + 4], (const uint32_t*)&af, (const uint32_t*)&bf1);
        }
    }
}
__device__ __forceinline__ void cchunk2(const char* st, float (&acc0)[32],
                                        float (&acc1)[32], int wm, int wn, int lane) {
    const char* Ab  = st + wm * 4 * 2048 + lane * 16;
    const char* Bb0 = st + A_STG + wn * 2 * 1024 + lane * 8;
    const char* Bb1 = Bb0 + B_STG;
#pragma unroll
    for (int ks = 0; ks < 4; ks++) {
        uint2 b00 = *(const uint2*)(Bb0 + ks * 256);
        uint2 b01 = *(const uint2*)(Bb0 + 1024 + ks * 256);
        uint2 b10 = *(const uint2*)(Bb1 + ks * 256);
        uint2 b11 = *(const uint2*)(Bb1 + 1024 + ks * 256);
#pragma unroll
        for (int mt = 0; mt < 4; mt++) {
            uint4 af = *(const uint4*)(Ab + mt * 2048 + ks * 512);
            mma8(&acc0[mt * 8],     (const uint32_t*)&af, (const uint32_t*)&b00);
            mma8(&acc0[mt * 8 + 4], (const uint32_t*)&af, (const uint32_t*)&b01);
            mma8(&acc1[mt * 8],     (const uint32_t*)&af, (const uint32_t*)&b10);
            mma8(&acc1[mt * 8 + 4], (const uint32_t*)&af, (const uint32_t*)&b11);
        }
    }
}

__global__ void __launch_bounds__(256, 1) scn_mma_kernel(
    const float* __restrict__ c_state, float* __restrict__ out) {
    extern __shared__ char smc[];
    const uint32_t sbase = smem_u32(smc);
    const int tid = threadIdx.x, lane = tid & 31, wid = tid >> 5;
    const int gid = lane >> 2, ctid = lane & 3;
    const int wm = wid >> 2, wn = wid & 3;       // warp grid 2(M) x 4(N)
    const int hcol0 = blockIdx.x * 16;           // CTA N = 64 (4 sections x 16)
    const int brow0 = blockIdx.y * 128;

    float axi[32] = {}, ahs[32] = {}, agi[32] = {}, ags[32] = {};

    const int blk = tid >> 5;   // 0..7: m16-block / n8-block index within tile
    const int sub = tid & 31;

    auto issue = [&](int g) {
        const int ph = g >> 5, kc = g & 31;
        const float* A  = (ph == 0) ? rA_core : (ph == 1) ? rA_h   : rA_concept;
        const float* B0 = (ph == 0) ? rW_in   : (ph == 1) ? rW_st  : rW_ci;
        uint32_t st = sbase + (uint32_t)(g & 3) * STAGE_BYTES;
        // A: m16-block (brow0/16 + blk), 2048 B contiguous, 64 B per thread
        {
            const float* s = A + ((size_t)((blockIdx.y * 8 + blk) * 32 + kc)) * 512 + sub * 16;
            uint32_t d = st + (uint32_t)(blk * 2048 + sub * 64);
#pragma unroll
            for (int i = 0; i < 4; i++) cpa16(d + i * 16, s + i * 4);
        }
        // B: n8-block = sec*128 + bx*2 + jb, 1024 B contiguous, 32 B per thread
        {
            int ntg = ((blk >> 1) << 7) + blockIdx.x * 2 + (blk & 1);
            const float* s = B0 + ((size_t)(ntg * 32 + kc)) * 256 + sub * 8;
            uint32_t d = st + A_STG + (uint32_t)(blk * 1024 + sub * 32);
#pragma unroll
            for (int i = 0; i < 2; i++) cpa16(d + i * 16, s + i * 4);
            if (ph == 2) {
                const float* s1 = rW_cs + ((size_t)(ntg * 32 + kc)) * 256 + sub * 8;
#pragma unroll
                for (int i = 0; i < 2; i++) cpa16(d + B_STG + i * 16, s1 + i * 4);
            }
        }
        CP_COMMIT();
    };

    issue(0); issue(1); issue(2);

    for (int g = 0; g < 96; g++) {
        CP_WAIT2();
        __syncthreads();
        if (g + 3 < 96) issue(g + 3);
        else            CP_COMMIT();   // empty group keeps pending count exact

        const char* st = smc + (size_t)(g & 3) * STAGE_BYTES;
        if (g < 32)      cchunk(st, axi, wm, wn, lane);
        else if (g < 64) cchunk(st, ahs, wm, wn, lane);
        else             cchunk2(st, agi, ags, wm, wn, lane);
        // slot (g+3)&3 == (g-1)&3: compute(g-1) finished before the barrier above.
    }
    __syncthreads();

    // ---- fused epilogue: hidden = sigmoid(gi*xi + gs*hs) staged in smem ----
    float* hid = (float*)smc;   // 128 x 65 floats
#pragma unroll
    for (int mt = 0; mt < 4; mt++)
#pragma unroll
        for (int nt = 0; nt < 2; nt++)
#pragma unroll
            for (int c = 0; c < 4; c++) {
                int i = mt * 8 + nt * 4 + c;
                int m = wm * 64 + mt * 16 + gid + ((c >> 1) ? 8 : 0);
                int n = wn * 16 + nt * 8 + ctid * 2 + (c & 1);
                float z = agi[i] * axi[i] + ags[i] * ahs[i];
                hid[m * HID_STRIDE + n] = 1.0f / (1.0f + expf(-z));
            }
    __syncthreads();

    // LSTM combine: local n = sec*16 + j; secs = i, f, o, c_cand
    {
        int m = tid >> 1;
        int j0 = (tid & 1) * 8;
        const float* row = hid + m * HID_STRIDE;
        size_t gbase = (size_t)(brow0 + m) * H_DIM + hcol0 + j0;
#pragma unroll
        for (int i = 0; i < 8; i++) {
            int j = j0 + i;
            float it = row[j];
            float ft = row[16 + j];
            float ot = row[32 + j];
            float cc = row[48 + j];
            float cs = c_state[gbase + i];
            float ct = it * cc + ft * cs;
            float ht = ot * tanhf(ct);
            out[gbase + i] = ht;
            out[(size_t)B_DIM * H_DIM + gbase + i] = ct;
        }
    }
}

// ---------------- tf32 round + fragment-major relayout pre-pass ----------------
// A': [mt(64)][kc(32)][ks(4)][lane(32)][4]  element (c): m = mt*16+gid+8*(c&1),
//                                           k = kc*32+ks*8+ctid+4*(c>>1)
__global__ void __launch_bounds__(256) cvtA_kernel(const float* __restrict__ src,
                                                   float4* __restrict__ dst, int ldk) {
    int i = blockIdx.x * 256 + threadIdx.x;          // 262144 total
    int lane = i & 31, ks = (i >> 5) & 3, kc = (i >> 7) & 31, mt = i >> 12;
    int gid = lane >> 2, ctid = lane & 3;
    int m = mt * 16 + gid;
    int kb = kc * 32 + ks * 8 + ctid;
    float v[4];
#pragma unroll
    for (int c = 0; c < 4; c++) {
        int mm = m + 8 * (c & 1);
        int kk = kb + 4 * (c >> 1);
        float x = (kk < ldk) ? src[(size_t)mm * ldk + kk] : 0.0f;
        v[c] = __uint_as_float(tf32r(x));
    }
    dst[i] = make_float4(v[0], v[1], v[2], v[3]);
}
// W': [nt(512)][kc(32)][ks(4)][lane(32)][2]  n = nt*8+gid, k = kc*32+ks*8+ctid+4*c
__global__ void __launch_bounds__(256) cvtW_kernel(const float* __restrict__ src,
                                                   float2* __restrict__ dst, int ldk) {
    int i = blockIdx.x * 256 + threadIdx.x;          // 2097152 total
    int lane = i & 31, ks = (i >> 5) & 3, kc = (i >> 7) & 31, nt = i >> 12;
    int gid = lane >> 2, ctid = lane & 3;
    int n = nt * 8 + gid;
    int k0 = kc * 32 + ks * 8 + ctid;
    float x0 = (k0 < ldk)     ? src[(size_t)n * ldk + k0]     : 0.0f;
    float x1 = (k0 + 4 < ldk) ? src[(size_t)n * ldk + k0 + 4] : 0.0f;
    dst[i] = make_float2(__uint_as_float(tf32r(x0)), __uint_as_float(tf32r(x1)));
}

extern "C" void kernel_launch(void* const* d_in, const int* in_sizes, int n_in,
                              void* d_out, int out_size) {
    const float* core_input = (const float*)d_in[0];
    const float* h_state    = (const float*)d_in[1];
    const float* c_state    = (const float*)d_in[2];
    const float* concept    = (const float*)d_in[3];
    const float* W_in       = (const float*)d_in[4];
    const float* W_st       = (const float*)d_in[5];
    const float* W_ci       = (const float*)d_in[6];
    const float* W_cs       = (const float*)d_in[7];
    float* out = (float*)d_out;

    static bool configured = false;
    if (!configured) {
        cudaFuncSetAttribute(scn_mma_kernel,
                             cudaFuncAttributeMaxDynamicSharedMemorySize, SMEM_BYTES);
        configured = true;
    }

    float *a0, *a1, *a2, *w0, *w1, *w2, *w3;
    cudaGetSymbolAddress((void**)&a0, rA_core);
    cudaGetSymbolAddress((void**)&a1, rA_h);
    cudaGetSymbolAddress((void**)&a2, rA_concept);
    cudaGetSymbolAddress((void**)&w0, rW_in);
    cudaGetSymbolAddress((void**)&w1, rW_st);
    cudaGetSymbolAddress((void**)&w2, rW_ci);
    cudaGetSymbolAddress((void**)&w3, rW_cs);

    cvtA_kernel<<<1024, 256>>>(core_input, (float4*)a0, 1024);
    cvtA_kernel<<<1024, 256>>>(h_state,    (float4*)a1, 1024);
    cvtA_kernel<<<1024, 256>>>(concept,    (float4*)a2, 1000);
    cvtW_kernel<<<8192, 256>>>(W_in, (float2*)w0, 1024);
    cvtW_kernel<<<8192, 256>>>(W_st, (float2*)w1, 1024);
    cvtW_kernel<<<8192, 256>>>(W_ci, (float2*)w2, 1000);
    cvtW_kernel<<<8192, 256>>>(W_cs, (float2*)w3, 1000);

    dim3 grid(64, 8);   // 64 hcol tiles x 8 batch tiles = 512 CTAs
    scn_mma_kernel<<<grid, 256, SMEM_BYTES>>>(c_state, out);
}

// round 9
// speedup vs baseline: 1.2768x; 1.2559x over previous
#include <cuda_runtime.h>
#include <cstdint>
#include <math.h>

#define B_DIM 1024
#define H_DIM 1024
#define KPAD  1024

// fragment-major blocks: A (m16-block, kchunk32) = 2048 B; W (n8-block, kchunk32) = 1024 B
#define A_STG 16384                       // 8 m16-blocks
#define B_STG 8192                        // 8 n8-blocks
#define STAGE_BYTES (A_STG + 2 * B_STG)   // 32768
#define NSTAGE 3
#define SMEM_BYTES (NSTAGE * STAGE_BYTES) // 98304
#define HID_STRIDE 65

// fragment-major, tf32-pre-rounded operands (K padded 1000 -> 1024 with zeros)
__device__ float rA_core[B_DIM * KPAD];
__device__ float rA_h[B_DIM * KPAD];
__device__ float rA_concept[B_DIM * KPAD];
__device__ float rW_in[4 * H_DIM * KPAD];
__device__ float rW_st[4 * H_DIM * KPAD];
__device__ float rW_ci[4 * H_DIM * KPAD];
__device__ float rW_cs[4 * H_DIM * KPAD];
// inter-phase accumulator spill (fragment layout, bit-exact round trip)
__device__ float g_xi[B_DIM * 4 * H_DIM];
__device__ float g_hs[B_DIM * 4 * H_DIM];

__device__ __forceinline__ uint32_t smem_u32(const void* p) {
    uint32_t a;
    asm("{ .reg .u64 t; cvta.to.shared.u64 t, %1; cvt.u32.u64 %0, t; }" : "=r"(a) : "l"(p));
    return a;
}
__device__ __forceinline__ void cpa16(uint32_t dst, const float* src) {
    asm volatile("cp.async.cg.shared.global [%0], [%1], 16;"
                 :: "r"(dst), "l"(__cvta_generic_to_global(src)) : "memory");
}
#define CP_COMMIT() asm volatile("cp.async.commit_group;" ::: "memory")
#define CP_WAIT1()  asm volatile("cp.async.wait_group 1;" ::: "memory")

__device__ __forceinline__ void mma8(float* d, const uint32_t* a, const uint32_t* b) {
    asm volatile(
        "mma.sync.aligned.m16n8k8.row.col.f32.tf32.tf32.f32 "
        "{%0,%1,%2,%3}, {%4,%5,%6,%7}, {%8,%9}, {%0,%1,%2,%3};"
        : "+f"(d[0]), "+f"(d[1]), "+f"(d[2]), "+f"(d[3])
        : "r"(a[0]), "r"(a[1]), "r"(a[2]), "r"(a[3]), "r"(b[0]), "r"(b[1]));
}
__device__ __forceinline__ uint32_t tf32r(float x) {
    uint32_t r;
    asm("cvt.rna.tf32.f32 %0, %1;" : "=r"(r) : "f"(x));
    return r;
}

// Warp tile 64(M) x 16(N); fragment loads are single LDS.128 / LDS.64.
__device__ __forceinline__ void cchunk(const char* st, float (&acc)[32],
                                       int wm, int wn, int lane) {
    const char* Ab = st + wm * 4 * 2048 + lane * 16;
    const char* Bb = st + A_STG + wn * 2 * 1024 + lane * 8;
#pragma unroll
    for (int ks = 0; ks < 4; ks++) {
        uint2 bf0 = *(const uint2*)(Bb + ks * 256);
        uint2 bf1 = *(const uint2*)(Bb + 1024 + ks * 256);
#pragma unroll
        for (int mt = 0; mt < 4; mt++) {
            uint4 af = *(const uint4*)(Ab + mt * 2048 + ks * 512);
            mma8(&acc[mt * 8],     (const uint32_t*)&af, (const uint32_t*)&bf0);
            mma8(&acc[mt * 8 + 4], (const uint32_t*)&af, (const uint32_t*)&bf1);
        }
    }
}
__device__ __forceinline__ void cchunk2(const char* st, float (&acc0)[32],
                                        float (&acc1)[32], int wm, int wn, int lane) {
    const char* Ab  = st + wm * 4 * 2048 + lane * 16;
    const char* Bb0 = st + A_STG + wn * 2 * 1024 + lane * 8;
    const char* Bb1 = Bb0 + B_STG;
#pragma unroll
    for (int ks = 0; ks < 4; ks++) {
        uint2 b00 = *(const uint2*)(Bb0 + ks * 256);
        uint2 b01 = *(const uint2*)(Bb0 + 1024 + ks * 256);
        uint2 b10 = *(const uint2*)(Bb1 + ks * 256);
        uint2 b11 = *(const uint2*)(Bb1 + 1024 + ks * 256);
#pragma unroll
        for (int mt = 0; mt < 4; mt++) {
            uint4 af = *(const uint4*)(Ab + mt * 2048 + ks * 512);
            mma8(&acc0[mt * 8],     (const uint32_t*)&af, (const uint32_t*)&b00);
            mma8(&acc0[mt * 8 + 4], (const uint32_t*)&af, (const uint32_t*)&b01);
            mma8(&acc1[mt * 8],     (const uint32_t*)&af, (const uint32_t*)&b10);
            mma8(&acc1[mt * 8 + 4], (const uint32_t*)&af, (const uint32_t*)&b11);
        }
    }
}

__global__ void __launch_bounds__(256, 2) scn_mma_kernel(
    const float* __restrict__ c_state, float* __restrict__ out) {
    extern __shared__ char smc[];
    const uint32_t sbase = smem_u32(smc);
    const int tid = threadIdx.x, lane = tid & 31, wid = tid >> 5;
    const int gid = lane >> 2, ctid = lane & 3;
    const int wm = wid >> 2, wn = wid & 3;       // warp grid 2(M) x 4(N)
    const int hcol0 = blockIdx.x * 16;           // CTA N = 64 (4 sections x 16)
    const int brow0 = blockIdx.y * 128;
    const int cta = blockIdx.y * 64 + blockIdx.x;
    const int blk = tid >> 5, sub = tid & 31;

    auto issue = [&](int g) {
        const int ph = g >> 5, kc = g & 31;
        const float* A  = (ph == 0) ? rA_core : (ph == 1) ? rA_h   : rA_concept;
        const float* B0 = (ph == 0) ? rW_in   : (ph == 1) ? rW_st  : rW_ci;
        uint32_t st = sbase + (uint32_t)(((uint32_t)g) % 3u) * STAGE_BYTES;
        {   // A: m16-block (brow0/16 + blk), 2048 B contiguous
            const float* s = A + ((size_t)((blockIdx.y * 8 + blk) * 32 + kc)) * 512 + sub * 16;
            uint32_t d = st + (uint32_t)(blk * 2048 + sub * 64);
#pragma unroll
            for (int i = 0; i < 4; i++) cpa16(d + i * 16, s + i * 4);
        }
        {   // B: n8-block = sec*128 + bx*2 + jb, 1024 B contiguous
            int ntg = ((blk >> 1) << 7) + blockIdx.x * 2 + (blk & 1);
            const float* s = B0 + ((size_t)(ntg * 32 + kc)) * 256 + sub * 8;
            uint32_t d = st + A_STG + (uint32_t)(blk * 1024 + sub * 32);
            cpa16(d, s);
            cpa16(d + 16, s + 4);
            if (ph == 2) {
                const float* s1 = rW_cs + ((size_t)(ntg * 32 + kc)) * 256 + sub * 8;
                cpa16(d + B_STG, s1);
                cpa16(d + B_STG + 16, s1 + 4);
            }
        }
        CP_COMMIT();
    };

    // pipeline step macro: wait stage g, refill g+2, return stage pointer
#define STEP(g)                                                            \
    CP_WAIT1();                                                            \
    __syncthreads();                                                       \
    if ((g) + 2 < 96) issue((g) + 2); else CP_COMMIT();                    \
    const char* st = smc + (size_t)(((uint32_t)(g)) % 3u) * STAGE_BYTES;

    const size_t fragbase = ((size_t)(cta * 8 + wid) * 8) * 32 + lane;

    issue(0); issue(1);

    {   // phase 0: xi = core @ W_in
        float axi[32] = {};
        for (int g = 0; g < 32; g++) { STEP(g); cchunk(st, axi, wm, wn, lane); }
        float4* xs = (float4*)g_xi;
#pragma unroll
        for (int t = 0; t < 8; t++)
            xs[fragbase + (size_t)t * 32] =
                make_float4(axi[t*4], axi[t*4+1], axi[t*4+2], axi[t*4+3]);
    }
    {   // phase 1: hs = h @ W_st
        float ahs[32] = {};
        for (int g = 32; g < 64; g++) { STEP(g); cchunk(st, ahs, wm, wn, lane); }
        float4* hs = (float4*)g_hs;
#pragma unroll
        for (int t = 0; t < 8; t++)
            hs[fragbase + (size_t)t * 32] =
                make_float4(ahs[t*4], ahs[t*4+1], ahs[t*4+2], ahs[t*4+3]);
    }
    // phase 2: gi = concept @ W_ci, gs = concept @ W_cs (shared A)
    float agi[32] = {}, ags[32] = {};
    for (int g = 64; g < 96; g++) { STEP(g); cchunk2(st, agi, ags, wm, wn, lane); }
#undef STEP
    __syncthreads();

    // ---- fused epilogue: hidden = sigmoid(gi*xi + gs*hs) staged in smem ----
    float* hid = (float*)smc;   // 128 x 65 floats
    {
        const float4* xs = (const float4*)g_xi;
        const float4* hs = (const float4*)g_hs;
#pragma unroll
        for (int t = 0; t < 8; t++) {
            float4 x4 = xs[fragbase + (size_t)t * 32];
            float4 h4 = hs[fragbase + (size_t)t * 32];
            const float zx[4] = {x4.x, x4.y, x4.z, x4.w};
            const float zh[4] = {h4.x, h4.y, h4.z, h4.w};
            int mt = t >> 1, nt = t & 1;
#pragma unroll
            for (int c = 0; c < 4; c++) {
                int i = mt * 8 + nt * 4 + c;
                float z = agi[i] * zx[c] + ags[i] * zh[c];
                int m = wm * 64 + mt * 16 + gid + ((c >> 1) ? 8 : 0);
                int n = wn * 16 + nt * 8 + ctid * 2 + (c & 1);
                hid[m * HID_STRIDE + n] = 1.0f / (1.0f + expf(-z));
            }
        }
    }
    __syncthreads();

    // LSTM combine: local n = sec*16 + j; secs = i, f, o, c_cand
    {
        int m = tid >> 1;
        int j0 = (tid & 1) * 8;
        const float* row = hid + m * HID_STRIDE;
        size_t gbase = (size_t)(brow0 + m) * H_DIM + hcol0 + j0;
#pragma unroll
        for (int i = 0; i < 8; i++) {
            int j = j0 + i;
            float it = row[j];
            float ft = row[16 + j];
            float ot = row[32 + j];
            float cc = row[48 + j];
            float cs = c_state[gbase + i];
            float ct = it * cc + ft * cs;
            float ht = ot * tanhf(ct);
            out[gbase + i] = ht;
            out[(size_t)B_DIM * H_DIM + gbase + i] = ct;
        }
    }
}

// -------- merged tf32 round + fragment-major relayout pre-pass (ONE launch) --------
// blocks [0, 3072): A-type, 1024 blocks per tensor (core, h, concept)
// blocks [3072, 35840): W-type, 8192 blocks per tensor (Win, Wst, Wci, Wcs)
__global__ void __launch_bounds__(256) cvt_all_kernel(
    const float* __restrict__ core_input, const float* __restrict__ h_state,
    const float* __restrict__ concept,
    const float* __restrict__ W_in, const float* __restrict__ W_st,
    const float* __restrict__ W_ci, const float* __restrict__ W_cs) {
    int bid = blockIdx.x;
    if (bid < 3072) {
        int t = bid >> 10;
        const float* src = (t == 0) ? core_input : (t == 1) ? h_state : concept;
        float4* dst = (float4*)((t == 0) ? rA_core : (t == 1) ? rA_h : rA_concept);
        int ldk = (t == 2) ? 1000 : 1024;
        int i = (bid & 1023) * 256 + threadIdx.x;
        int lane = i & 31, ks = (i >> 5) & 3, kc = (i >> 7) & 31, mt = i >> 12;
        int gid = lane >> 2, ctid = lane & 3;
        int m = mt * 16 + gid;
        int kb = kc * 32 + ks * 8 + ctid;
        float v[4];
#pragma unroll
        for (int c = 0; c < 4; c++) {
            int mm = m + 8 * (c & 1);
            int kk = kb + 4 * (c >> 1);
            float x = (kk < ldk) ? src[(size_t)mm * ldk + kk] : 0.0f;
            v[c] = __uint_as_float(tf32r(x));
        }
        dst[i] = make_float4(v[0], v[1], v[2], v[3]);
    } else {
        int b2 = bid - 3072;
        int t = b2 >> 13;
        const float* src = (t == 0) ? W_in : (t == 1) ? W_st : (t == 2) ? W_ci : W_cs;
        float2* dst = (float2*)((t == 0) ? rW_in : (t == 1) ? rW_st
                                : (t == 2) ? rW_ci : rW_cs);
        int ldk = (t >= 2) ? 1000 : 1024;
        int i = (b2 & 8191) * 256 + threadIdx.x;
        int lane = i & 31, ks = (i >> 5) & 3, kc = (i >> 7) & 31, nt = i >> 12;
        int gid = lane >> 2, ctid = lane & 3;
        int n = nt * 8 + gid;
        int k0 = kc * 32 + ks * 8 + ctid;
        float x0 = (k0 < ldk)     ? src[(size_t)n * ldk + k0]     : 0.0f;
        float x1 = (k0 + 4 < ldk) ? src[(size_t)n * ldk + k0 + 4] : 0.0f;
        dst[i] = make_float2(__uint_as_float(tf32r(x0)), __uint_as_float(tf32r(x1)));
    }
}

extern "C" void kernel_launch(void* const* d_in, const int* in_sizes, int n_in,
                              void* d_out, int out_size) {
    const float* core_input = (const float*)d_in[0];
    const float* h_state    = (const float*)d_in[1];
    const float* c_state    = (const float*)d_in[2];
    const float* concept    = (const float*)d_in[3];
    const float* W_in       = (const float*)d_in[4];
    const float* W_st       = (const float*)d_in[5];
    const float* W_ci       = (const float*)d_in[6];
    const float* W_cs       = (const float*)d_in[7];
    float* out = (float*)d_out;

    static bool configured = false;
    if (!configured) {
        cudaFuncSetAttribute(scn_mma_kernel,
                             cudaFuncAttributeMaxDynamicSharedMemorySize, SMEM_BYTES);
        configured = true;
    }

    cvt_all_kernel<<<35840, 256>>>(core_input, h_state, concept,
                                   W_in, W_st, W_ci, W_cs);

    dim3 grid(64, 8);   // 64 hcol tiles x 8 batch tiles = 512 CTAs
    scn_mma_kernel<<<grid, 256, SMEM_BYTES>>>(c_state, out);
}

// round 10
// speedup vs baseline: 1.3075x; 1.0240x over previous
#include <cuda_runtime.h>
#include <cstdint>
#include <math.h>

#define B_DIM 1024
#define H_DIM 1024
#define KPAD  1024

// fragment-major blocks: A (m16-block, kchunk32) = 2048 B; W (n8-block, kchunk32) = 1024 B
#define A_STG 16384                       // 8 m16-blocks (M=128)
#define B_STG 16384                       // 16 n8-blocks (N=128)
#define STAGE_BYTES (A_STG + B_STG)       // 32768
#define NSTAGE 3
#define SMEM_BYTES (NSTAGE * STAGE_BYTES) // 98304
#define HIDS 132

// fragment-major, tf32-pre-rounded operands (K padded 1000 -> 1024 with zeros)
__device__ float rA_core[B_DIM * KPAD];
__device__ float rA_h[B_DIM * KPAD];
__device__ float rA_concept[B_DIM * KPAD];
__device__ float rW_in[4 * H_DIM * KPAD];
__device__ float rW_st[4 * H_DIM * KPAD];
__device__ float rW_ci[4 * H_DIM * KPAD];
__device__ float rW_cs[4 * H_DIM * KPAD];
// inter-phase accumulator spills (fragment layout, bit-exact round trip)
__device__ float g_xi[B_DIM * 4 * H_DIM];
__device__ float g_hs[B_DIM * 4 * H_DIM];
__device__ float g_gi[B_DIM * 4 * H_DIM];

__device__ __forceinline__ uint32_t smem_u32(const void* p) {
    uint32_t a;
    asm("{ .reg .u64 t; cvta.to.shared.u64 t, %1; cvt.u32.u64 %0, t; }" : "=r"(a) : "l"(p));
    return a;
}
__device__ __forceinline__ void cpa16(uint32_t dst, const float* src) {
    asm volatile("cp.async.cg.shared.global [%0], [%1], 16;"
                 :: "r"(dst), "l"(__cvta_generic_to_global(src)) : "memory");
}
#define CP_COMMIT() asm volatile("cp.async.commit_group;" ::: "memory")
#define CP_WAIT1()  asm volatile("cp.async.wait_group 1;" ::: "memory")

__device__ __forceinline__ void mma8(float* d, const uint32_t* a, const uint32_t* b) {
    asm volatile(
        "mma.sync.aligned.m16n8k8.row.col.f32.tf32.tf32.f32 "
        "{%0,%1,%2,%3}, {%4,%5,%6,%7}, {%8,%9}, {%0,%1,%2,%3};"
        : "+f"(d[0]), "+f"(d[1]), "+f"(d[2]), "+f"(d[3])
        : "r"(a[0]), "r"(a[1]), "r"(a[2]), "r"(a[3]), "r"(b[0]), "r"(b[1]));
}
__device__ __forceinline__ uint32_t tf32r(float x) {
    uint32_t r;
    asm("cvt.rna.tf32.f32 %0, %1;" : "=r"(r) : "f"(x));
    return r;
}

// Warp tile 64(M) x 32(N); fragment loads are single LDS.128 / LDS.64.
__device__ __forceinline__ void cchunk(const char* st, float (&acc)[64],
                                       int wm, int wn, int lane) {
    const char* Ab = st + wm * 4 * 2048 + lane * 16;
    const char* Bb = st + A_STG + wn * 4 * 1024 + lane * 8;
#pragma unroll
    for (int ks = 0; ks < 4; ks++) {
        uint2 bf[4];
#pragma unroll
        for (int nt = 0; nt < 4; nt++)
            bf[nt] = *(const uint2*)(Bb + nt * 1024 + ks * 256);
#pragma unroll
        for (int mt = 0; mt < 4; mt++) {
            uint4 af = *(const uint4*)(Ab + mt * 2048 + ks * 512);
#pragma unroll
            for (int nt = 0; nt < 4; nt++)
                mma8(&acc[(mt * 4 + nt) * 4], (const uint32_t*)&af,
                     (const uint32_t*)&bf[nt]);
        }
    }
}

__global__ void __launch_bounds__(256, 2) scn_mma_kernel(
    const float* __restrict__ c_state, float* __restrict__ out) {
    extern __shared__ char smc[];
    const uint32_t sbase = smem_u32(smc);
    const int tid = threadIdx.x, lane = tid & 31, wid = tid >> 5;
    const int gid = lane >> 2, ctid = lane & 3;
    const int wm = wid >> 2, wn = wid & 3;       // warp grid 2(M) x 4(N); wn == gate section
    const int hcol0 = blockIdx.x * 32;           // 32 h-cols, all 4 sections resident (N=128)
    const int brow0 = blockIdx.y * 128;
    const int cta = blockIdx.y * 32 + blockIdx.x;

    auto issue = [&](int g) {
        const int ph = g >> 5, kc = g & 31;
        const float* A  = (ph == 0) ? rA_core : (ph == 1) ? rA_h : rA_concept;
        const float* B0 = (ph == 0) ? rW_in : (ph == 1) ? rW_st
                        : (ph == 2) ? rW_ci : rW_cs;
        uint32_t st = sbase + (uint32_t)(((uint32_t)g) % 3u) * STAGE_BYTES;
        {   // A: 8 m16-blocks, blk = tid>>5, 64 B/thread
            const int blk = tid >> 5, sub = tid & 31;
            const float* s = A + ((size_t)((blockIdx.y * 8 + blk) * 32 + kc)) * 512 + sub * 16;
            uint32_t d = st + (uint32_t)(blk * 2048 + sub * 64);
#pragma unroll
            for (int i = 0; i < 4; i++) cpa16(d + i * 16, s + i * 4);
        }
        {   // B: 16 n8-blocks, bblk = tid>>4 = sec*4 + jb, 64 B/thread
            const int bblk = tid >> 4, bsub = tid & 15;
            int ntg = ((bblk >> 2) << 7) + blockIdx.x * 4 + (bblk & 3);
            const float* s = B0 + ((size_t)(ntg * 32 + kc)) * 256 + bsub * 16;
            uint32_t d = st + A_STG + (uint32_t)(bblk * 1024 + bsub * 64);
#pragma unroll
            for (int i = 0; i < 4; i++) cpa16(d + i * 16, s + i * 4);
        }
        CP_COMMIT();
    };

#define STEP(g)                                                            \
    CP_WAIT1();                                                            \
    __syncthreads();                                                       \
    if ((g) + 2 < 128) issue((g) + 2); else CP_COMMIT();                   \
    const char* st = smc + (size_t)(((uint32_t)(g)) % 3u) * STAGE_BYTES;

    const size_t fragbase = ((size_t)(cta * 8 + wid) * 16) * 32 + lane;

    issue(0); issue(1);

    {   // phase 0: xi = core @ W_in -> spill
        float acc[64] = {};
        for (int g = 0; g < 32; g++) { STEP(g); cchunk(st, acc, wm, wn, lane); }
        float4* sp = (float4*)g_xi;
#pragma unroll
        for (int t = 0; t < 16; t++)
            sp[fragbase + (size_t)t * 32] =
                make_float4(acc[t*4], acc[t*4+1], acc[t*4+2], acc[t*4+3]);
    }
    {   // phase 1: hs = h @ W_st -> spill
        float acc[64] = {};
        for (int g = 32; g < 64; g++) { STEP(g); cchunk(st, acc, wm, wn, lane); }
        float4* sp = (float4*)g_hs;
#pragma unroll
        for (int t = 0; t < 16; t++)
            sp[fragbase + (size_t)t * 32] =
                make_float4(acc[t*4], acc[t*4+1], acc[t*4+2], acc[t*4+3]);
    }
    {   // phase 2: gi = concept @ W_ci -> spill
        float acc[64] = {};
        for (int g = 64; g < 96; g++) { STEP(g); cchunk(st, acc, wm, wn, lane); }
        float4* sp = (float4*)g_gi;
#pragma unroll
        for (int t = 0; t < 16; t++)
            sp[fragbase + (size_t)t * 32] =
                make_float4(acc[t*4], acc[t*4+1], acc[t*4+2], acc[t*4+3]);
    }
    // phase 3: gs = concept @ W_cs (kept in regs)
    float ags[64] = {};
    for (int g = 96; g < 128; g++) { STEP(g); cchunk(st, ags, wm, wn, lane); }
#undef STEP
    __syncthreads();

    // ---- fused epilogue: hidden = sigmoid(gi*xi + gs*hs) staged in smem ----
    float* hid = (float*)smc;   // 128 x HIDS floats (67.6 KB)
    {
        const float4* xs = (const float4*)g_xi;
        const float4* hs = (const float4*)g_hs;
        const float4* gs = (const float4*)g_gi;
#pragma unroll
        for (int t = 0; t < 16; t++) {
            float4 x4 = xs[fragbase + (size_t)t * 32];
            float4 h4 = hs[fragbase + (size_t)t * 32];
            float4 g4 = gs[fragbase + (size_t)t * 32];
            const float zx[4] = {x4.x, x4.y, x4.z, x4.w};
            const float zh[4] = {h4.x, h4.y, h4.z, h4.w};
            const float zg[4] = {g4.x, g4.y, g4.z, g4.w};
            int mt = t >> 2, nt = t & 3;
#pragma unroll
            for (int c = 0; c < 4; c++) {
                float z = zg[c] * zx[c] + ags[t * 4 + c] * zh[c];
                int m = wm * 64 + mt * 16 + gid + ((c >> 1) ? 8 : 0);
                int n = wn * 32 + nt * 8 + ctid * 2 + (c & 1);
                hid[m * HIDS + n] = 1.0f / (1.0f + expf(-z));
            }
        }
    }
    __syncthreads();

    // ---- LSTM combine: hid[m][sec*32 + j], secs = i, f, o, c_cand ----
    {
        int m = tid >> 1;
        int j0 = (tid & 1) * 16;
        const float* row = hid + m * HIDS;
        size_t gbase = (size_t)(brow0 + m) * H_DIM + hcol0 + j0;
#pragma unroll
        for (int q = 0; q < 4; q++) {
            float4 hv, cv;
            float* ph = (float*)&hv;
            float* pc = (float*)&cv;
#pragma unroll
            for (int r = 0; r < 4; r++) {
                int j = j0 + q * 4 + r;
                float it = row[j];
                float ft = row[32 + j];
                float ot = row[64 + j];
                float cc = row[96 + j];
                float cs = c_state[gbase - j0 + j];
                float ct = it * cc + ft * cs;
                pc[r] = ct;
                ph[r] = ot * tanhf(ct);
            }
            *(float4*)&out[gbase + q * 4] = hv;
            *(float4*)&out[(size_t)B_DIM * H_DIM + gbase + q * 4] = cv;
        }
    }
}

// -------- merged tf32 round + fragment-major relayout pre-pass (ONE launch) --------
__global__ void __launch_bounds__(256) cvt_all_kernel(
    const float* __restrict__ core_input, const float* __restrict__ h_state,
    const float* __restrict__ concept,
    const float* __restrict__ W_in, const float* __restrict__ W_st,
    const float* __restrict__ W_ci, const float* __restrict__ W_cs) {
    int bid = blockIdx.x;
    if (bid < 3072) {
        int t = bid >> 10;
        const float* src = (t == 0) ? core_input : (t == 1) ? h_state : concept;
        float4* dst = (float4*)((t == 0) ? rA_core : (t == 1) ? rA_h : rA_concept);
        int ldk = (t == 2) ? 1000 : 1024;
        int i = (bid & 1023) * 256 + threadIdx.x;
        int lane = i & 31, ks = (i >> 5) & 3, kc = (i >> 7) & 31, mt = i >> 12;
        int gid = lane >> 2, ctid = lane & 3;
        int m = mt * 16 + gid;
        int kb = kc * 32 + ks * 8 + ctid;
        float v[4];
#pragma unroll
        for (int c = 0; c < 4; c++) {
            int mm = m + 8 * (c & 1);
            int kk = kb + 4 * (c >> 1);
            float x = (kk < ldk) ? src[(size_t)mm * ldk + kk] : 0.0f;
            v[c] = __uint_as_float(tf32r(x));
        }
        dst[i] = make_float4(v[0], v[1], v[2], v[3]);
    } else {
        int b2 = bid - 3072;
        int t = b2 >> 13;
        const float* src = (t == 0) ? W_in : (t == 1) ? W_st : (t == 2) ? W_ci : W_cs;
        float2* dst = (float2*)((t == 0) ? rW_in : (t == 1) ? rW_st
                                : (t == 2) ? rW_ci : rW_cs);
        int ldk = (t >= 2) ? 1000 : 1024;
        int i = (b2 & 8191) * 256 + threadIdx.x;
        int lane = i & 31, ks = (i >> 5) & 3, kc = (i >> 7) & 31, nt = i >> 12;
        int gid = lane >> 2, ctid = lane & 3;
        int n = nt * 8 + gid;
        int k0 = kc * 32 + ks * 8 + ctid;
        float x0 = (k0 < ldk)     ? src[(size_t)n * ldk + k0]     : 0.0f;
        float x1 = (k0 + 4 < ldk) ? src[(size_t)n * ldk + k0 + 4] : 0.0f;
        dst[i] = make_float2(__uint_as_float(tf32r(x0)), __uint_as_float(tf32r(x1)));
    }
}

extern "C" void kernel_launch(void* const* d_in, const int* in_sizes, int n_in,
                              void* d_out, int out_size) {
    const float* core_input = (const float*)d_in[0];
    const float* h_state    = (const float*)d_in[1];
    const float* c_state    = (const float*)d_in[2];
    const float* concept    = (const float*)d_in[3];
    const float* W_in       = (const float*)d_in[4];
    const float* W_st       = (const float*)d_in[5];
    const float* W_ci       = (const float*)d_in[6];
    const float* W_cs       = (const float*)d_in[7];
    float* out = (float*)d_out;

    static bool configured = false;
    if (!configured) {
        cudaFuncSetAttribute(scn_mma_kernel,
                             cudaFuncAttributeMaxDynamicSharedMemorySize, SMEM_BYTES);
        configured = true;
    }

    cvt_all_kernel<<<35840, 256>>>(core_input, h_state, concept,
                                   W_in, W_st, W_ci, W_cs);

    dim3 grid(32, 8);   // 32 hcol tiles x 8 batch tiles = 256 CTAs (2/SM, one wave)
    scn_mma_kernel<<<grid, 256, SMEM_BYTES>>>(c_state, out);
}

// round 12
// speedup vs baseline: 2.3696x; 1.8123x over previous
#include <cuda_runtime.h>
#include <cuda_fp16.h>
#include <cstdint>
#include <math.h>

#define B_DIM 1024
#define H_DIM 1024

// fp16 fragment-major blocks, K-chunk = 64:
//   A (m16-block, kchunk64) = 4 ks x 32 lanes x 8 halves = 2048 B
//   W (n8-block,  kchunk64) = 4 ks x 32 lanes x 4 halves = 1024 B
#define A_STG 16384                       // 8 m16-blocks (M=128)
#define B_STG 16384                       // 16 n8-blocks (N=128)
#define STAGE_BYTES (A_STG + B_STG)       // 32768
#define NSTAGE 3
#define SMEM_BYTES (NSTAGE * STAGE_BYTES) // 98304 -> 2 CTAs/SM
#define HIDS 132

// fp16 fragment-major operands (K padded 1000 -> 1024 with zeros)
__device__ __half hA_core[B_DIM * 1024];
__device__ __half hA_h[B_DIM * 1024];
__device__ __half hA_concept[B_DIM * 1024];
__device__ __half hW_in[4 * H_DIM * 1024];
__device__ __half hW_st[4 * H_DIM * 1024];
__device__ __half hW_ci[4 * H_DIM * 1024];
__device__ __half hW_cs[4 * H_DIM * 1024];
// inter-phase f32 accumulator spills (bit-exact round trip)
__device__ float g_xi[B_DIM * 4 * H_DIM];
__device__ float g_hs[B_DIM * 4 * H_DIM];
__device__ float g_gi[B_DIM * 4 * H_DIM];

__device__ __forceinline__ uint32_t smem_u32(const void* p) {
    uint32_t a;
    asm("{ .reg .u64 t; cvta.to.shared.u64 t, %1; cvt.u32.u64 %0, t; }" : "=r"(a) : "l"(p));
    return a;
}
__device__ __forceinline__ void cpa16(uint32_t dst, const void* src) {
    asm volatile("cp.async.cg.shared.global [%0], [%1], 16;"
                 :: "r"(dst), "l"(__cvta_generic_to_global(src)) : "memory");
}
#define CP_COMMIT() asm volatile("cp.async.commit_group;" ::: "memory")
#define CP_WAIT1()  asm volatile("cp.async.wait_group 1;" ::: "memory")

__device__ __forceinline__ void mma16(float* d, const uint32_t* a, const uint32_t* b) {
    asm volatile(
        "mma.sync.aligned.m16n8k16.row.col.f32.f16.f16.f32 "
        "{%0,%1,%2,%3}, {%4,%5,%6,%7}, {%8,%9}, {%0,%1,%2,%3};"
        : "+f"(d[0]), "+f"(d[1]), "+f"(d[2]), "+f"(d[3])
        : "r"(a[0]), "r"(a[1]), "r"(a[2]), "r"(a[3]), "r"(b[0]), "r"(b[1]));
}

// Warp tile 64(M) x 32(N), K=64 chunk (4 mma K-steps of 16).
__device__ __forceinline__ void cchunk(const char* st, float (&acc)[64],
                                       int wm, int wn, int lane) {
    const char* Ab = st + wm * 4 * 2048 + lane * 16;
    const char* Bb = st + A_STG + wn * 4 * 1024 + lane * 8;
#pragma unroll
    for (int ks = 0; ks < 4; ks++) {
        uint2 bf[4];
#pragma unroll
        for (int nt = 0; nt < 4; nt++)
            bf[nt] = *(const uint2*)(Bb + nt * 1024 + ks * 256);
#pragma unroll
        for (int mt = 0; mt < 4; mt++) {
            uint4 af = *(const uint4*)(Ab + mt * 2048 + ks * 512);
#pragma unroll
            for (int nt = 0; nt < 4; nt++)
                mma16(&acc[(mt * 4 + nt) * 4], (const uint32_t*)&af,
                      (const uint32_t*)&bf[nt]);
        }
    }
}

__global__ void __launch_bounds__(256, 2) scn_mma_kernel(
    const float* __restrict__ c_state, float* __restrict__ out) {
    extern __shared__ char smc[];
    const uint32_t sbase = smem_u32(smc);
    const int tid = threadIdx.x, lane = tid & 31, wid = tid >> 5;
    const int gid = lane >> 2, ctid = lane & 3;
    const int wm = wid >> 2, wn = wid & 3;       // warp grid 2(M) x 4(N); wn == gate section
    const int hcol0 = blockIdx.x * 32;
    const int brow0 = blockIdx.y * 128;
    const int cta = blockIdx.y * 32 + blockIdx.x;

    auto issue = [&](int g) {
        const int ph = g >> 4, kc = g & 15;
        const __half* A  = (ph == 0) ? hA_core : (ph == 1) ? hA_h : hA_concept;
        const __half* B0 = (ph == 0) ? hW_in : (ph == 1) ? hW_st
                         : (ph == 2) ? hW_ci : hW_cs;
        uint32_t st = sbase + (uint32_t)(((uint32_t)g) % 3u) * STAGE_BYTES;
        {   // A: 8 m16-blocks (2048 B each), blk = tid>>5, 64 B/thread
            const int blk = tid >> 5, sub = tid & 31;
            const __half* s = A + ((size_t)((blockIdx.y * 8 + blk) * 16 + kc)) * 1024 + sub * 32;
            uint32_t d = st + (uint32_t)(blk * 2048 + sub * 64);
#pragma unroll
            for (int i = 0; i < 4; i++) cpa16(d + i * 16, s + i * 8);
        }
        {   // B: 16 n8-blocks (1024 B each), bblk = tid>>4 = sec*4 + jb, 64 B/thread
            const int bblk = tid >> 4, bsub = tid & 15;
            int ntg = ((bblk >> 2) << 7) + blockIdx.x * 4 + (bblk & 3);
            const __half* s = B0 + ((size_t)(ntg * 16 + kc)) * 512 + bsub * 32;
            uint32_t d = st + A_STG + (uint32_t)(bblk * 1024 + bsub * 64);
#pragma unroll
            for (int i = 0; i < 4; i++) cpa16(d + i * 16, s + i * 8);
        }
        CP_COMMIT();
    };

#define STEP(g)                                                            \
    CP_WAIT1();                                                            \
    __syncthreads();                                                       \
    if ((g) + 2 < 64) issue((g) + 2); else CP_COMMIT();                    \
    const char* st = smc + (size_t)(((uint32_t)(g)) % 3u) * STAGE_BYTES;

    const size_t fragbase = ((size_t)(cta * 8 + wid) * 16) * 32 + lane;

    issue(0); issue(1);

    {   // phase 0: xi = core @ W_in -> spill
        float acc[64] = {};
        for (int g = 0; g < 16; g++) { STEP(g); cchunk(st, acc, wm, wn, lane); }
        float4* sp = (float4*)g_xi;
#pragma unroll
        for (int t = 0; t < 16; t++)
            sp[fragbase + (size_t)t * 32] =
                make_float4(acc[t*4], acc[t*4+1], acc[t*4+2], acc[t*4+3]);
    }
    {   // phase 1: hs = h @ W_st -> spill
        float acc[64] = {};
        for (int g = 16; g < 32; g++) { STEP(g); cchunk(st, acc, wm, wn, lane); }
        float4* sp = (float4*)g_hs;
#pragma unroll
        for (int t = 0; t < 16; t++)
            sp[fragbase + (size_t)t * 32] =
                make_float4(acc[t*4], acc[t*4+1], acc[t*4+2], acc[t*4+3]);
    }
    {   // phase 2: gi = concept @ W_ci -> spill
        float acc[64] = {};
        for (int g = 32; g < 48; g++) { STEP(g); cchunk(st, acc, wm, wn, lane); }
        float4* sp = (float4*)g_gi;
#pragma unroll
        for (int t = 0; t < 16; t++)
            sp[fragbase + (size_t)t * 32] =
                make_float4(acc[t*4], acc[t*4+1], acc[t*4+2], acc[t*4+3]);
    }
    // phase 3: gs = concept @ W_cs (kept in regs)
    float ags[64] = {};
    for (int g = 48; g < 64; g++) { STEP(g); cchunk(st, ags, wm, wn, lane); }
#undef STEP
    __syncthreads();

    // ---- fused epilogue: hidden = sigmoid(gi*xi + gs*hs) staged in smem ----
    float* hid = (float*)smc;   // 128 x HIDS floats
    {
        const float4* xs = (const float4*)g_xi;
        const float4* hs = (const float4*)g_hs;
        const float4* gs = (const float4*)g_gi;
#pragma unroll
        for (int t = 0; t < 16; t++) {
            float4 x4 = xs[fragbase + (size_t)t * 32];
            float4 h4 = hs[fragbase + (size_t)t * 32];
            float4 g4 = gs[fragbase + (size_t)t * 32];
            const float zx[4] = {x4.x, x4.y, x4.z, x4.w};
            const float zh[4] = {h4.x, h4.y, h4.z, h4.w};
            const float zg[4] = {g4.x, g4.y, g4.z, g4.w};
            int mt = t >> 2, nt = t & 3;
#pragma unroll
            for (int c = 0; c < 4; c++) {
                float z = zg[c] * zx[c] + ags[t * 4 + c] * zh[c];
                int m = wm * 64 + mt * 16 + gid + ((c >> 1) ? 8 : 0);
                int n = wn * 32 + nt * 8 + ctid * 2 + (c & 1);
                hid[m * HIDS + n] = 1.0f / (1.0f + expf(-z));
            }
        }
    }
    __syncthreads();

    // ---- LSTM combine: hid[m][sec*32 + j], secs = i, f, o, c_cand ----
    {
        int m = tid >> 1;
        int j0 = (tid & 1) * 16;
        const float* row = hid + m * HIDS;
        size_t gbase = (size_t)(brow0 + m) * H_DIM + hcol0 + j0;
#pragma unroll
        for (int q = 0; q < 4; q++) {
            float4 hv, cv;
            float* ph = (float*)&hv;
            float* pc = (float*)&cv;
#pragma unroll
            for (int r = 0; r < 4; r++) {
                int j = j0 + q * 4 + r;
                float it = row[j];
                float ft = row[32 + j];
                float ot = row[64 + j];
                float cc = row[96 + j];
                float cs = c_state[gbase - j0 + j];
                float ct = it * cc + ft * cs;
                pc[r] = ct;
                ph[r] = ot * tanhf(ct);
            }
            *(float4*)&out[gbase + q * 4] = hv;
            *(float4*)&out[(size_t)B_DIM * H_DIM + gbase + q * 4] = cv;
        }
    }
}

// -------- merged fp16 convert + fragment-major relayout pre-pass (ONE launch) --------
// A': [mt(64)][kc(16)][ks(4)][lane(32)][8 halves]
//   halves: (m,k) (m,k+1) (m+8,k) (m+8,k+1) (m,k+8) (m,k+9) (m+8,k+8) (m+8,k+9)
//   with m = mt*16+gid, k = kc*64+ks*16+2*ctid
// W': [nt(512)][kc(16)][ks(4)][lane(32)][4 halves]: n = nt*8+gid, k,k+1,k+8,k+9
__global__ void __launch_bounds__(256) cvt_all_kernel(
    const float* __restrict__ core_input, const float* __restrict__ h_state,
    const float* __restrict__ concept,
    const float* __restrict__ W_in, const float* __restrict__ W_st,
    const float* __restrict__ W_ci, const float* __restrict__ W_cs) {
    int bid = blockIdx.x;
    if (bid < 1536) {   // A-type: 512 blocks per tensor
        int t = bid / 512;
        const float* src = (t == 0) ? core_input : (t == 1) ? h_state : concept;
        uint4* dst = (uint4*)((t == 0) ? hA_core : (t == 1) ? hA_h : hA_concept);
        int ldk = (t == 2) ? 1000 : 1024;
        int i = (bid - t * 512) * 256 + threadIdx.x;   // 131072 per tensor
        int lane = i & 31, ks = (i >> 5) & 3, kc = (i >> 7) & 15, mt = i >> 11;
        int gid = lane >> 2, ctid = lane & 3;
        int m = mt * 16 + gid;
        int k = kc * 64 + ks * 16 + 2 * ctid;
        __half2 p[4];
#pragma unroll
        for (int q = 0; q < 4; q++) {     // q: (mrow, khi) pairs in order h01,h23,h45,h67
            int mm = m + 8 * (q & 1);
            int kk = k + 8 * (q >> 1);
            float x0 = (kk < ldk)     ? src[(size_t)mm * ldk + kk]     : 0.0f;
            float x1 = (kk + 1 < ldk) ? src[(size_t)mm * ldk + kk + 1] : 0.0f;
            p[q] = __floats2half2_rn(x0, x1);
        }
        dst[i] = *(const uint4*)p;
    } else {            // W-type: 4096 blocks per tensor
        int b2 = bid - 1536;
        int t = b2 >> 12;
        const float* src = (t == 0) ? W_in : (t == 1) ? W_st : (t == 2) ? W_ci : W_cs;
        uint2* dst = (uint2*)((t == 0) ? hW_in : (t == 1) ? hW_st
                              : (t == 2) ? hW_ci : hW_cs);
        int ldk = (t >= 2) ? 1000 : 1024;
        int i = (b2 & 4095) * 256 + threadIdx.x;       // 1048576 per tensor
        int lane = i & 31, ks = (i >> 5) & 3, kc = (i >> 7) & 15, nt = i >> 11;
        int gid = lane >> 2, ctid = lane & 3;
        int n = nt * 8 + gid;
        int k = kc * 64 + ks * 16 + 2 * ctid;
        __half2 p[2];
#pragma unroll
        for (int q = 0; q < 2; q++) {
            int kk = k + 8 * q;
            float x0 = (kk < ldk)     ? src[(size_t)n * ldk + kk]     : 0.0f;
            float x1 = (kk + 1 < ldk) ? src[(size_t)n * ldk + kk + 1] : 0.0f;
            p[q] = __floats2half2_rn(x0, x1);
        }
        dst[i] = *(const uint2*)p;
    }
}

extern "C" void kernel_launch(void* const* d_in, const int* in_sizes, int n_in,
                              void* d_out, int out_size) {
    const float* core_input = (const float*)d_in[0];
    const float* h_state    = (const float*)d_in[1];
    const float* c_state    = (const float*)d_in[2];
    const float* concept    = (const float*)d_in[3];
    const float* W_in       = (const float*)d_in[4];
    const float* W_st       = (const float*)d_in[5];
    const float* W_ci       = (const float*)d_in[6];
    const float* W_cs       = (const float*)d_in[7];
    float* out = (float*)d_out;

    static bool configured = false;
    if (!configured) {
        cudaFuncSetAttribute(scn_mma_kernel,
                             cudaFuncAttributeMaxDynamicSharedMemorySize, SMEM_BYTES);
        configured = true;
    }

    cvt_all_kernel<<<1536 + 4 * 4096, 256>>>(core_input, h_state, concept,
                                             W_in, W_st, W_ci, W_cs);

    dim3 grid(32, 8);   // 32 hcol tiles x 8 batch tiles = 256 CTAs (2/SM, one wave)
    scn_mma_kernel<<<grid, 256, SMEM_BYTES>>>(c_state, out);
}